// round 15
// baseline (speedup 1.0000x reference)
#include <cuda_runtime.h>
#include <cuda_fp16.h>
#include <math.h>
#include <stdint.h>

// Problem constants
#define B_SZ  512
#define DIN   64
#define DCL   4998
#define DTRF  5120
#define PADN  61
#define PP    32
#define EE    160
#define DOUT  3000
#define M2    (B_SZ * PP)          // 16384 rows of 160

// Global scratch
__device__ float g_cl[B_SZ * DCL];
__device__ float g_q [M2 * EE];
__device__ float g_k [M2 * EE];
__device__ float g_v [M2 * EE];
__device__ float g_h [M2 * EE];
__device__ __align__(256) __half g_yh[M2 * EE];        // y in fp16 (k3 A operand)
__device__ __align__(256) __half g_wh[DOUT * DTRF];    // lin_w in fp16 (k3 B operand)
__device__ __align__(256) __half g_wqh[EE * EE];       // wq fp16 [f][e]
__device__ __align__(256) __half g_wkh[EE * EE];
__device__ __align__(256) __half g_wvh[EE * EE];

// ---------------------------------------------------------------------------
// helpers
// ---------------------------------------------------------------------------
__device__ __forceinline__ uint32_t f2tf32(float f) {
    uint32_t u;
    asm("cvt.rna.tf32.f32 %0, %1;" : "=r"(u) : "f"(f));
    return u;
}
__device__ __forceinline__ void mma_tf32(float* c, const uint32_t* a,
                                         const uint32_t* b) {
    asm volatile(
        "mma.sync.aligned.m16n8k8.row.col.f32.tf32.tf32.f32 "
        "{%0,%1,%2,%3}, {%4,%5,%6,%7}, {%8,%9}, {%0,%1,%2,%3};\n"
        : "+f"(c[0]), "+f"(c[1]), "+f"(c[2]), "+f"(c[3])
        : "r"(a[0]), "r"(a[1]), "r"(a[2]), "r"(a[3]),
          "r"(b[0]), "r"(b[1]));
}
__device__ __forceinline__ uint32_t pack2h(float a, float b) {
    __half2 h = __floats2half2_rn(a, b);
    return *(uint32_t*)&h;
}
__device__ __forceinline__ void mma_f16(float* c, const uint32_t* a,
                                        uint32_t b0, uint32_t b1) {
    asm volatile(
        "mma.sync.aligned.m16n8k16.row.col.f32.f16.f16.f32 "
        "{%0,%1,%2,%3}, {%4,%5,%6,%7}, {%8,%9}, {%0,%1,%2,%3};\n"
        : "+f"(c[0]), "+f"(c[1]), "+f"(c[2]), "+f"(c[3])
        : "r"(a[0]), "r"(a[1]), "r"(a[2]), "r"(a[3]),
          "r"(b0), "r"(b1));
}
__device__ __forceinline__ void ldsm_x4(uint32_t& r0, uint32_t& r1,
                                        uint32_t& r2, uint32_t& r3,
                                        uint32_t addr) {
    asm volatile(
        "ldmatrix.sync.aligned.m8n8.x4.shared.b16 {%0,%1,%2,%3}, [%4];"
        : "=r"(r0), "=r"(r1), "=r"(r2), "=r"(r3) : "r"(addr));
}
__device__ __forceinline__ void cp16(uint32_t dst, const void* src) {
    asm volatile("cp.async.cg.shared.global [%0], [%1], 16;"
                 :: "r"(dst), "l"(src));
}

// ---------------------------------------------------------------------------
// Kernel 0: convert lin_w -> g_wh (fp16).
// ---------------------------------------------------------------------------
__global__ __launch_bounds__(256) void k0_wh(const float* __restrict__ w)
{
    size_t i = ((size_t)blockIdx.x * 256 + threadIdx.x) * 8;
    float4 a = *(const float4*)(w + i);
    float4 b = *(const float4*)(w + i + 4);
    uint4 u;
    u.x = pack2h(a.x, a.y); u.y = pack2h(a.z, a.w);
    u.z = pack2h(b.x, b.y); u.w = pack2h(b.z, b.w);
    *(uint4*)(g_wh + i) = u;
}

// ---------------------------------------------------------------------------
// Kernel 0b: wq/wk/wv -> fp16 copies. 3 * 25600 elems.
// ---------------------------------------------------------------------------
__global__ __launch_bounds__(256) void k0b_wsmall(
    const float* __restrict__ wq, const float* __restrict__ wk,
    const float* __restrict__ wv)
{
    int gid = blockIdx.x * 256 + threadIdx.x;
    int mat = gid / (EE * EE);
    int i   = gid % (EE * EE);
    if (mat == 0)      g_wqh[i] = __float2half(wq[i]);
    else if (mat == 1) g_wkh[i] = __float2half(wk[i]);
    else               g_wvh[i] = __float2half(wv[i]);
}

// ---------------------------------------------------------------------------
// Kernel 1: cl = (x*std + mean) @ mat   64x128 tile, 8x4 per thread,
// 2-deep software pipeline on mat loads.
// ---------------------------------------------------------------------------
__global__ __launch_bounds__(256) void k1_clgemm(
    const float* __restrict__ x, const float* __restrict__ stdv,
    const float* __restrict__ meanv, const float* __restrict__ mat)
{
    __shared__ float u_s[64 * 64];
    const int rbase = blockIdx.y * 64;
    const int cbase = blockIdx.x * 128;
    const int tid = threadIdx.x;

    for (int idx = tid; idx < 64 * 64; idx += 256) {
        int r = idx >> 6, k = idx & 63;
        u_s[idx] = x[(rbase + r) * DIN + k] * stdv[k] + meanv[k];
    }
    __syncthreads();

    const int ty = tid >> 5;
    const int tx = tid & 31;
    int   c[4];  bool cv[4];
#pragma unroll
    for (int j = 0; j < 4; j++) { c[j] = cbase + tx + 32 * j; cv[j] = (c[j] < DCL); }

    float acc[8][4] = {};
    float bcur[2][4], bnxt[2][4];
#pragma unroll
    for (int kk = 0; kk < 2; kk++)
#pragma unroll
        for (int j = 0; j < 4; j++)
            bcur[kk][j] = cv[j] ? mat[kk * DCL + c[j]] : 0.f;

    for (int k = 0; k < 64; k += 2) {
        if (k + 2 < 64) {
#pragma unroll
            for (int kk = 0; kk < 2; kk++)
#pragma unroll
                for (int j = 0; j < 4; j++)
                    bnxt[kk][j] = cv[j] ? mat[(k + 2 + kk) * DCL + c[j]] : 0.f;
        }
#pragma unroll
        for (int kk = 0; kk < 2; kk++) {
            float a[8];
#pragma unroll
            for (int i = 0; i < 8; i++) a[i] = u_s[(ty + 8 * i) * 64 + k + kk];
#pragma unroll
            for (int i = 0; i < 8; i++)
#pragma unroll
                for (int j = 0; j < 4; j++)
                    acc[i][j] += a[i] * bcur[kk][j];
        }
#pragma unroll
        for (int kk = 0; kk < 2; kk++)
#pragma unroll
            for (int j = 0; j < 4; j++)
                bcur[kk][j] = bnxt[kk][j];
    }
#pragma unroll
    for (int i = 0; i < 8; i++) {
        int row = rbase + ty + 8 * i;
#pragma unroll
        for (int j = 0; j < 4; j++)
            if (cv[j]) g_cl[row * DCL + c[j]] = acc[i][j];
    }
}

// ---------------------------------------------------------------------------
// Kernel 2b: fused LayerNorm + QKV GEMM (fp16 mma), occupancy-optimized.
// grid (M2/64, 3): blockIdx.y = matrix. 256 threads = 8 warps.
// warps: wm = warp&3 (m16 tile), wn = warp>>2 (N half: 10 n8 tiles).
// smem: Ah[64][168] fp16 (21504 B) + Bs[2][160][24] fp16 (15360 B) = 36864 B
// ---------------------------------------------------------------------------
#define QK_ALD 168
#define QK_BLD 24
__global__ __launch_bounds__(256) void k2b_qkv(
    const float* __restrict__ ln_g, const float* __restrict__ ln_b,
    const float* __restrict__ bq, const float* __restrict__ bk,
    const float* __restrict__ bv)
{
    extern __shared__ __align__(16) __half smb[];
    __half (*Ah)[QK_ALD] = (__half(*)[QK_ALD])smb;
    __half (*Bs)[160][QK_BLD] = (__half(*)[160][QK_BLD])(smb + 64 * QK_ALD);
    __shared__ float red[40];

    const int t    = threadIdx.x;
    const int lane = t & 31;
    const int warp = t >> 5;
    const int wm   = warp & 3;
    const int wn   = warp >> 2;
    const int g    = lane >> 2;
    const int tg   = lane & 3;
    const int mb   = blockIdx.x * 64;
    const int b0   = mb >> 5;
    const int mat  = blockIdx.y;

    const __half* Wh  = (mat == 0) ? g_wqh : (mat == 1) ? g_wkh : g_wvh;
    const float* bias = (mat == 0) ? bq : (mat == 1) ? bk : bv;
    float*       outp = (mat == 0) ? g_q : (mat == 1) ? g_k : g_v;

    // B chunk loader: 160 rows x 2 half-chunks = 320 cp16, 256 threads
    auto issueB = [&](int kc, int buf) {
#pragma unroll
        for (int i = 0; i < 2; i++) {
            int idx = t + i * 256;
            if (idx < 320) {
                int n = idx >> 1, hf = idx & 1;
                uint32_t dst = (uint32_t)__cvta_generic_to_shared(
                    &Bs[buf][n][hf * 8]);
                cp16(dst, Wh + (size_t)n * EE + kc * 16 + hf * 8);
            }
        }
        asm volatile("cp.async.commit_group;" ::: "memory");
    };
    issueB(0, 0);

    // ---- phase 1: LN stats ----
    const float* cl0 = g_cl + (size_t)b0 * DCL;
    const float* cl1 = g_cl + (size_t)(b0 + 1) * DCL;
    float s0 = 0.f, q0 = 0.f, s1 = 0.f, q1 = 0.f;
    for (int i = t; i < 2560; i += 256) {
        int r = i / 40, c4 = i % 40;
        int hb = r >> 5, p = r & 31;
        int d = p * EE + c4 * 4;
        const float* clr = hb ? cl1 : cl0;
        float ls = 0.f, lq = 0.f;
#pragma unroll
        for (int j = 0; j < 4; j++) {
            int dd = d + j;
            float v = (dd >= PADN && dd < PADN + DCL) ? clr[dd - PADN] : 0.f;
            ls += v; lq += v * v;
        }
        if (hb) { s1 += ls; q1 += lq; } else { s0 += ls; q0 += lq; }
    }
#pragma unroll
    for (int o = 16; o > 0; o >>= 1) {
        s0 += __shfl_xor_sync(~0u, s0, o);
        q0 += __shfl_xor_sync(~0u, q0, o);
        s1 += __shfl_xor_sync(~0u, s1, o);
        q1 += __shfl_xor_sync(~0u, q1, o);
    }
    if (lane == 0) {
        red[warp * 4 + 0] = s0; red[warp * 4 + 1] = q0;
        red[warp * 4 + 2] = s1; red[warp * 4 + 3] = q1;
    }
    __syncthreads();
    if (t < 2) {
        float s = 0.f, qq = 0.f;
        for (int w = 0; w < 8; w++) {
            s  += red[w * 4 + 2 * t];
            qq += red[w * 4 + 2 * t + 1];
        }
        float mu  = s / (float)DTRF;
        float var = qq / (float)DTRF - mu * mu;
        red[32 + t * 2]     = mu;
        red[32 + t * 2 + 1] = rsqrtf(var + 1e-5f);
    }
    __syncthreads();

    // ---- phase 2: normalize, pack fp16 -> Ah ----
    {
        float mu0 = red[32], rs0 = red[33], mu1 = red[34], rs1 = red[35];
        for (int i = t; i < 2560; i += 256) {
            int r = i / 40, c4 = i % 40;
            int hb = r >> 5, p = r & 31;
            int d = p * EE + c4 * 4;
            const float* clr = hb ? cl1 : cl0;
            float mu = hb ? mu1 : mu0, rs = hb ? rs1 : rs0;
            float v[4];
#pragma unroll
            for (int j = 0; j < 4; j++) {
                int dd = d + j;
                v[j] = (dd >= PADN && dd < PADN + DCL) ? clr[dd - PADN] : 0.f;
            }
            float4 gg = *(const float4*)&ln_g[d];
            float4 bb = *(const float4*)&ln_b[d];
            uint2 u;
            u.x = pack2h((v[0] - mu) * rs * gg.x + bb.x,
                         (v[1] - mu) * rs * gg.y + bb.y);
            u.y = pack2h((v[2] - mu) * rs * gg.z + bb.z,
                         (v[3] - mu) * rs * gg.w + bb.w);
            *(uint2*)&Ah[r][c4 * 4] = u;
        }
    }
    __syncthreads();

    // ---- GEMM: 10 k16 chunks, B double-buffered via cp.async ----
    float acc[10][4] = {};
    for (int kc = 0; kc < 10; kc++) {
        const int buf = kc & 1;
        asm volatile("cp.async.wait_group 0;" ::: "memory");
        __syncthreads();
        if (kc + 1 < 10) issueB(kc + 1, buf ^ 1);

        uint32_t af[4];
        {
            uint32_t addr = (uint32_t)__cvta_generic_to_shared(
                &Ah[wm * 16 + (lane & 15)][kc * 16 + (lane >> 4) * 8]);
            ldsm_x4(af[0], af[1], af[2], af[3], addr);
        }
        uint32_t bf[5][4];
#pragma unroll
        for (int nh = 0; nh < 5; nh++) {
            uint32_t addr = (uint32_t)__cvta_generic_to_shared(
                &Bs[buf][wn * 80 + nh * 16 + (lane & 7) + ((lane >> 4) & 1) * 8]
                   [((lane >> 3) & 1) * 8]);
            ldsm_x4(bf[nh][0], bf[nh][1], bf[nh][2], bf[nh][3], addr);
        }
#pragma unroll
        for (int ni = 0; ni < 10; ni++) {
            const int nh = ni >> 1, sub = ni & 1;
            mma_f16(acc[ni], af, bf[nh][sub * 2], bf[nh][sub * 2 + 1]);
        }
    }

    const int r0 = mb + wm * 16 + g;
#pragma unroll
    for (int ni = 0; ni < 10; ni++) {
        const int n0 = wn * 80 + ni * 8 + tg * 2;
        const float bb0 = bias[n0], bb1 = bias[n0 + 1];
        outp[(size_t)r0 * EE + n0]           = acc[ni][0] + bb0;
        outp[(size_t)r0 * EE + n0 + 1]       = acc[ni][1] + bb1;
        outp[(size_t)(r0 + 8) * EE + n0]     = acc[ni][2] + bb0;
        outp[(size_t)(r0 + 8) * EE + n0 + 1] = acc[ni][3] + bb1;
    }
}

// ---------------------------------------------------------------------------
// Kernel 2c: attention per batch row. 512 blocks x 256 threads.
// ---------------------------------------------------------------------------
__global__ __launch_bounds__(256) void k2c_attn()
{
    extern __shared__ float sm2c[];
    float (*sq)[164] = (float(*)[164])sm2c;
    float (*kt)[36]  = (float(*)[36]) (sm2c + 32 * 164);
    float (*sv)[164] = (float(*)[164])(sm2c + 32 * 164 + 160 * 36);
    float (*att)[33] = (float(*)[33]) (sm2c + 64 * 164 + 160 * 36);

    const int b = blockIdx.x;
    const int t = threadIdx.x;
    const float inv_scale = rsqrtf(160.0f);
    const size_t base = (size_t)b * PP * EE;

#pragma unroll
    for (int i = 0; i < 5; i++) {
        int idx = t + i * 256;
        int p = idx / 40, c4 = idx % 40;
        uint32_t dst = (uint32_t)__cvta_generic_to_shared(&sv[p][c4 * 4]);
        cp16(dst, g_v + base + p * EE + c4 * 4);
    }
    asm volatile("cp.async.commit_group;" ::: "memory");

#pragma unroll
    for (int i = 0; i < 5; i++) {
        int idx = t + i * 256;
        int p = idx / 40, c4 = idx % 40;
        float4 qv = *(const float4*)&g_q[base + p * EE + c4 * 4];
        *(float4*)&sq[p][c4 * 4] = make_float4(qv.x * inv_scale, qv.y * inv_scale,
                                               qv.z * inv_scale, qv.w * inv_scale);
        float4 kv = *(const float4*)&g_k[base + p * EE + c4 * 4];
        kt[c4 * 4 + 0][p] = kv.x;
        kt[c4 * 4 + 1][p] = kv.y;
        kt[c4 * 4 + 2][p] = kv.z;
        kt[c4 * 4 + 3][p] = kv.w;
    }
    __syncthreads();

    {
        const int p = t >> 3, q4 = t & 7;
        float a0 = 0.f, a1 = 0.f, a2 = 0.f, a3 = 0.f;
#pragma unroll 4
        for (int e4 = 0; e4 < 40; e4++) {
            float4 qv = *(const float4*)&sq[p][e4 * 4];
            float4 k0 = *(const float4*)&kt[e4 * 4 + 0][q4 * 4];
            float4 k1 = *(const float4*)&kt[e4 * 4 + 1][q4 * 4];
            float4 k2 = *(const float4*)&kt[e4 * 4 + 2][q4 * 4];
            float4 k3 = *(const float4*)&kt[e4 * 4 + 3][q4 * 4];
            a0 += qv.x * k0.x + qv.y * k1.x + qv.z * k2.x + qv.w * k3.x;
            a1 += qv.x * k0.y + qv.y * k1.y + qv.z * k2.y + qv.w * k3.y;
            a2 += qv.x * k0.z + qv.y * k1.z + qv.z * k2.z + qv.w * k3.z;
            a3 += qv.x * k0.w + qv.y * k1.w + qv.z * k2.w + qv.w * k3.w;
        }
        att[p][q4 * 4 + 0] = a0; att[p][q4 * 4 + 1] = a1;
        att[p][q4 * 4 + 2] = a2; att[p][q4 * 4 + 3] = a3;
    }
    __syncthreads();

    if (t < 128) {
        const int q = t >> 2, pg = t & 3;
        float m = -1e30f;
#pragma unroll
        for (int i = 0; i < 8; i++) m = fmaxf(m, att[pg * 8 + i][q]);
        m = fmaxf(m, __shfl_xor_sync(~0u, m, 1));
        m = fmaxf(m, __shfl_xor_sync(~0u, m, 2));
        float s = 0.f;
        float ev[8];
#pragma unroll
        for (int i = 0; i < 8; i++) {
            ev[i] = __expf(att[pg * 8 + i][q] - m);
            s += ev[i];
        }
        s += __shfl_xor_sync(~0u, s, 1);
        s += __shfl_xor_sync(~0u, s, 2);
        float inv = 1.f / s;
#pragma unroll
        for (int i = 0; i < 8; i++) att[pg * 8 + i][q] = ev[i] * inv;
    }
    asm volatile("cp.async.wait_group 0;" ::: "memory");
    __syncthreads();

    const float* clrow = g_cl + (size_t)b * DCL;
#pragma unroll
    for (int j = 0; j < 5; j++) {
        int idx4 = t + j * 256;
        int p = idx4 / 40, e4 = idx4 % 40;
        float4 a = make_float4(0.f, 0.f, 0.f, 0.f);
#pragma unroll
        for (int q = 0; q < 32; q++) {
            float w = att[p][q];
            float4 vv = *(const float4*)&sv[q][e4 * 4];
            a.x += w * vv.x; a.y += w * vv.y;
            a.z += w * vv.z; a.w += w * vv.w;
        }
        int d = p * EE + e4 * 4;
        float cl0 = (d + 0 >= PADN && d + 0 < PADN + DCL) ? clrow[d + 0 - PADN] : 0.f;
        float cl1 = (d + 1 >= PADN && d + 1 < PADN + DCL) ? clrow[d + 1 - PADN] : 0.f;
        float cl2 = (d + 2 >= PADN && d + 2 < PADN + DCL) ? clrow[d + 2 - PADN] : 0.f;
        float cl3 = (d + 3 >= PADN && d + 3 < PADN + DCL) ? clrow[d + 3 - PADN] : 0.f;
        *(float4*)&g_h[base + d] =
            make_float4(a.x + cl0, a.y + cl1, a.z + cl2, a.w + cl3);
    }
}

// ---------------------------------------------------------------------------
// Kernel 2d: BT GEMM + Supact + residual (tf32 mma). BM=64, grid 256.
// Writes g_yh (fp16).
// ---------------------------------------------------------------------------
__global__ __launch_bounds__(256) void k2d_bt(
    const float* __restrict__ bt_w, const float* __restrict__ bt_b,
    const float* __restrict__ bt_gain, const float* __restrict__ bt_bias,
    const float* __restrict__ sup_gamma, const float* __restrict__ sup_beta)
{
    extern __shared__ uint32_t sm2d[];
    uint32_t (*As)[164]     = (uint32_t(*)[164])sm2d;
    uint32_t (*Bs)[16][168] = (uint32_t(*)[16][168])(sm2d + 64 * 164);

    const int t    = threadIdx.x;
    const int lane = t & 31;
    const int warp = t >> 5;
    const int wm   = warp & 3;
    const int wn   = warp >> 2;
    const int g    = lane >> 2;
    const int tg   = lane & 3;
    const int mb   = blockIdx.x * 64;
    const float btg = bt_gain[0], btb = bt_bias[0];

    float4 bst[3];
#pragma unroll
    for (int i = 0; i < 3; i++) {
        int idx = t + i * 256;
        if (idx < 640) {
            int e = idx / 40, f4 = idx % 40;
            bst[i] = *(const float4*)&bt_w[(size_t)e * EE + f4 * 4];
        }
    }

    for (int i = t; i < 2560; i += 256) {
        int r = i / 40, c4 = i % 40;
        float4 v = *(const float4*)&g_h[(size_t)(mb + r) * EE + c4 * 4];
        uint4 u = make_uint4(f2tf32(v.x * btg + btb), f2tf32(v.y * btg + btb),
                             f2tf32(v.z * btg + btb), f2tf32(v.w * btg + btb));
        *(uint4*)&As[r][c4 * 4] = u;
    }

    float acc[10][4] = {};
    for (int kc = 0; kc < 10; kc++) {
        const int buf = kc & 1;
#pragma unroll
        for (int i = 0; i < 3; i++) {
            int idx = t + i * 256;
            if (idx < 640) {
                int e = idx / 40, f4 = idx % 40;
                uint4 u = make_uint4(f2tf32(bst[i].x), f2tf32(bst[i].y),
                                     f2tf32(bst[i].z), f2tf32(bst[i].w));
                *(uint4*)&Bs[buf][e][f4 * 4] = u;
            }
        }
        __syncthreads();
        if (kc + 1 < 10) {
            int k0 = (kc + 1) * 16;
#pragma unroll
            for (int i = 0; i < 3; i++) {
                int idx = t + i * 256;
                if (idx < 640) {
                    int e = idx / 40, f4 = idx % 40;
                    bst[i] = *(const float4*)&bt_w[(size_t)(k0 + e) * EE + f4 * 4];
                }
            }
        }
#pragma unroll
        for (int ks = 0; ks < 2; ks++) {
            const int kA = kc * 16 + ks * 8;
            uint32_t af[4];
            af[0] = As[wm * 16 + g][kA + tg];
            af[1] = As[wm * 16 + g + 8][kA + tg];
            af[2] = As[wm * 16 + g][kA + tg + 4];
            af[3] = As[wm * 16 + g + 8][kA + tg + 4];
#pragma unroll
            for (int j = 0; j < 10; j++) {
                const int n8 = wn * 10 + j;
                uint32_t bf[2];
                bf[0] = Bs[buf][ks * 8 + tg][n8 * 8 + g];
                bf[1] = Bs[buf][ks * 8 + tg + 4][n8 * 8 + g];
                mma_tf32(acc[j], af, bf);
            }
        }
    }

    const int r0 = mb + wm * 16 + g;
#pragma unroll
    for (int j = 0; j < 10; j++) {
        const int n0 = (wn * 10 + j) * 8 + tg * 2;
        const float bb0 = bt_b[n0], bb1 = bt_b[n0 + 1];
#pragma unroll
        for (int half = 0; half < 2; half++) {
            const int row = r0 + half * 8;
            const int gi0 = (row & 31) * EE + n0;
            float o0 = acc[j][half * 2 + 0] + bb0;
            float o1 = acc[j][half * 2 + 1] + bb1;
            float gm0 = sup_gamma[gi0],     gm1 = sup_gamma[gi0 + 1];
            float sb0 = sup_beta[gi0],      sb1 = sup_beta[gi0 + 1];
            float h0  = g_h[(size_t)row * EE + n0];
            float h1  = g_h[(size_t)row * EE + n0 + 1];
            float s0 = 1.f / (1.f + __expf(-sb0 * o0));
            float s1 = 1.f / (1.f + __expf(-sb1 * o1));
            float y0 = (gm0 + s0 * (1.f - gm0)) * o0 + h0;
            float y1 = (gm1 + s1 * (1.f - gm1)) * o1 + h1;
            *(__half2*)&g_yh[(size_t)row * EE + n0] = __floats2half2_rn(y0, y1);
        }
    }
}

// ---------------------------------------------------------------------------
// Kernel 3: z = y @ lin_w^T  (fp16 in, cp.async double-buffered, ldmatrix)
// BM=128, BN=96, BK=64, 256 threads, grid (32,4)=128 CTAs — ONE wave.
// ---------------------------------------------------------------------------
#define K3_BM 128
#define K3_BN 96
#define K3_BK 64
#define K3_LDH 72
#define K3_NIT (DTRF / K3_BK)    // 80
#define K3_A_OFF(buf) ((buf) * K3_BM * K3_LDH)
#define K3_B_OFF(buf) (2 * K3_BM * K3_LDH + (buf) * K3_BN * K3_LDH)
#define K3_SMEM ((2 * K3_BM * K3_LDH + 2 * K3_BN * K3_LDH) * 2)   // 64512 B

__global__ __launch_bounds__(256) void k3_f16(
    const float* __restrict__ lin_b,
    const float* __restrict__ og_p, const float* __restrict__ ob_p,
    float* __restrict__ out)
{
    extern __shared__ __align__(16) __half smh[];
    const uint32_t sbase = (uint32_t)__cvta_generic_to_shared(smh);

    const int t    = threadIdx.x;
    const int lane = t & 31;
    const int warp = t >> 5;
    const int wm   = warp >> 1;   // 0..3 -> rows wm*32
    const int wn   = warp & 1;    // 0..1 -> cols wn*48
    const int g    = lane >> 2;
    const int tg   = lane & 3;

    const int mbase = blockIdx.y * K3_BM;
    const int nbase = blockIdx.x * K3_BN;

    const int arow0 = t >> 3;     // 0..31, +32 per i
    const int ach   = t & 7;

    float acc[2][6][4] = {};

    auto issue = [&](int it, int buf) {
        const int kh = it * K3_BK;
#pragma unroll
        for (int i = 0; i < 4; i++) {
            int row = arow0 + i * 32;
            uint32_t dst = sbase +
                (uint32_t)(K3_A_OFF(buf) + row * K3_LDH + ach * 8) * 2;
            cp16(dst, g_yh + (size_t)(mbase + row) * DTRF + kh + ach * 8);
        }
#pragma unroll
        for (int i = 0; i < 3; i++) {
            int row = arow0 + i * 32;
            int br = nbase + row;
            if (br >= DOUT) br = 0;
            uint32_t dst = sbase +
                (uint32_t)(K3_B_OFF(buf) + row * K3_LDH + ach * 8) * 2;
            cp16(dst, g_wh + (size_t)br * DTRF + kh + ach * 8);
        }
        asm volatile("cp.async.commit_group;" ::: "memory");
    };

    issue(0, 0);

    for (int it = 0; it < K3_NIT; it++) {
        const int buf = it & 1;
        asm volatile("cp.async.wait_group 0;" ::: "memory");
        __syncthreads();
        if (it + 1 < K3_NIT) issue(it + 1, buf ^ 1);

#pragma unroll
        for (int ks = 0; ks < 4; ks++) {
            const int k0 = ks * 16;
            uint32_t af[2][4];
#pragma unroll
            for (int mi = 0; mi < 2; mi++) {
                const int rb = wm * 32 + mi * 16;
                uint32_t addr = sbase + (uint32_t)(K3_A_OFF(buf) +
                    (rb + (lane & 15)) * K3_LDH + k0 + (lane >> 4) * 8) * 2;
                ldsm_x4(af[mi][0], af[mi][1], af[mi][2], af[mi][3], addr);
            }
            uint32_t bf[3][4];
#pragma unroll
            for (int nh = 0; nh < 3; nh++) {
                const int nb = wn * 48 + nh * 16;
                uint32_t addr = sbase + (uint32_t)(K3_B_OFF(buf) +
                    (nb + (lane & 7) + ((lane >> 4) & 1) * 8) * K3_LDH +
                    k0 + ((lane >> 3) & 1) * 8) * 2;
                ldsm_x4(bf[nh][0], bf[nh][1], bf[nh][2], bf[nh][3], addr);
            }
#pragma unroll
            for (int mi = 0; mi < 2; mi++)
#pragma unroll
                for (int ni = 0; ni < 6; ni++) {
                    const int nh = ni >> 1, sub = ni & 1;
                    mma_f16(acc[mi][ni], af[mi],
                            bf[nh][sub * 2], bf[nh][sub * 2 + 1]);
                }
        }
    }

    const float og = og_p[0], ob = ob_p[0];
#pragma unroll
    for (int mi = 0; mi < 2; mi++) {
        const int m0 = mbase + wm * 32 + mi * 16 + g;
#pragma unroll
        for (int ni = 0; ni < 6; ni++) {
            const int n0 = nbase + wn * 48 + ni * 8 + tg * 2;
            if (n0 + 1 < DOUT) {
                const float lb0 = lin_b[n0], lb1 = lin_b[n0 + 1];
                out[(size_t)m0 * DOUT + n0]           = (acc[mi][ni][0] + lb0) * og + ob;
                out[(size_t)m0 * DOUT + n0 + 1]       = (acc[mi][ni][1] + lb1) * og + ob;
                out[(size_t)(m0 + 8) * DOUT + n0]     = (acc[mi][ni][2] + lb0) * og + ob;
                out[(size_t)(m0 + 8) * DOUT + n0 + 1] = (acc[mi][ni][3] + lb1) * og + ob;
            } else if (n0 < DOUT) {
                const float lb0 = lin_b[n0];
                out[(size_t)m0 * DOUT + n0]       = (acc[mi][ni][0] + lb0) * og + ob;
                out[(size_t)(m0 + 8) * DOUT + n0] = (acc[mi][ni][2] + lb0) * og + ob;
            }
        }
    }
}

// ---------------------------------------------------------------------------
extern "C" void kernel_launch(void* const* d_in, const int* in_sizes, int n_in,
                              void* d_out, int out_size)
{
    const float* x         = (const float*)d_in[0];
    const float* stdv      = (const float*)d_in[1];
    const float* meanv     = (const float*)d_in[2];
    const float* mat       = (const float*)d_in[3];
    const float* ln_g      = (const float*)d_in[4];
    const float* ln_b      = (const float*)d_in[5];
    const float* wq        = (const float*)d_in[6];
    const float* bq        = (const float*)d_in[7];
    const float* wk        = (const float*)d_in[8];
    const float* bk        = (const float*)d_in[9];
    const float* wv        = (const float*)d_in[10];
    const float* bv        = (const float*)d_in[11];
    const float* bt_w      = (const float*)d_in[12];
    const float* bt_b      = (const float*)d_in[13];
    const float* bt_gain   = (const float*)d_in[14];
    const float* bt_bias   = (const float*)d_in[15];
    const float* sup_gamma = (const float*)d_in[16];
    const float* sup_beta  = (const float*)d_in[17];
    const float* lin_w     = (const float*)d_in[18];
    const float* lin_b     = (const float*)d_in[19];
    const float* out_gain  = (const float*)d_in[20];
    const float* out_bias  = (const float*)d_in[21];
    float* out = (float*)d_out;

    const int smem2b = (64 * QK_ALD + 2 * 160 * QK_BLD) * 2;           // 36864
    const int smem2c = (64 * 164 + 160 * 36 + 32 * 33) * 4;            // 69248
    const int smem2d = (64 * 164 + 2 * 16 * 168) * 4;                  // 63488

    cudaFuncSetAttribute(k2b_qkv, cudaFuncAttributeMaxDynamicSharedMemorySize, smem2b);
    cudaFuncSetAttribute(k2c_attn, cudaFuncAttributeMaxDynamicSharedMemorySize, smem2c);
    cudaFuncSetAttribute(k2d_bt,  cudaFuncAttributeMaxDynamicSharedMemorySize, smem2d);
    cudaFuncSetAttribute(k3_f16,  cudaFuncAttributeMaxDynamicSharedMemorySize, K3_SMEM);

    k0_wh    <<<DOUT * DTRF / (8 * 256), 256>>>(lin_w);
    k0b_wsmall<<<3 * EE * EE / 256, 256>>>(wq, wk, wv);
    k1_clgemm<<<dim3(40, 8), 256>>>(x, stdv, meanv, mat);
    k2b_qkv <<<dim3(M2 / 64, 3), 256, smem2b>>>(ln_g, ln_b, bq, bk, bv);
    k2c_attn<<<B_SZ, 256, smem2c>>>();
    k2d_bt  <<<M2 / 64, 256, smem2d>>>(bt_w, bt_b, bt_gain, bt_bias,
                                       sup_gamma, sup_beta);
    k3_f16  <<<dim3((DOUT + K3_BN - 1) / K3_BN, B_SZ / K3_BM), 256, K3_SMEM>>>(
        lin_b, out_gain, out_bias, out);
}

// round 16
// speedup vs baseline: 1.0396x; 1.0396x over previous
#include <cuda_runtime.h>
#include <cuda_fp16.h>
#include <math.h>
#include <stdint.h>

// Problem constants
#define B_SZ  512
#define DIN   64
#define DCL   4998
#define DTRF  5120
#define PADN  61
#define PP    32
#define EE    160
#define DOUT  3000
#define M2    (B_SZ * PP)          // 16384 rows of 160

// Global scratch
__device__ __align__(256) float g_clp[B_SZ * DTRF];    // padded cl (zeros in pads)
__device__ float g_q [M2 * EE];
__device__ float g_k [M2 * EE];
__device__ float g_v [M2 * EE];
__device__ float g_h [M2 * EE];
__device__ __align__(256) __half g_xnh[M2 * EE];       // LN output fp16
__device__ __align__(256) __half g_yh[M2 * EE];        // y fp16 (k3 A)
__device__ __align__(256) __half g_wh[DOUT * DTRF];    // lin_w fp16 (k3 B)
__device__ __align__(256) __half g_wqh[EE * EE];
__device__ __align__(256) __half g_wkh[EE * EE];
__device__ __align__(256) __half g_wvh[EE * EE];

// ---------------------------------------------------------------------------
// helpers
// ---------------------------------------------------------------------------
__device__ __forceinline__ uint32_t f2tf32(float f) {
    uint32_t u;
    asm("cvt.rna.tf32.f32 %0, %1;" : "=r"(u) : "f"(f));
    return u;
}
__device__ __forceinline__ void mma_tf32(float* c, const uint32_t* a,
                                         const uint32_t* b) {
    asm volatile(
        "mma.sync.aligned.m16n8k8.row.col.f32.tf32.tf32.f32 "
        "{%0,%1,%2,%3}, {%4,%5,%6,%7}, {%8,%9}, {%0,%1,%2,%3};\n"
        : "+f"(c[0]), "+f"(c[1]), "+f"(c[2]), "+f"(c[3])
        : "r"(a[0]), "r"(a[1]), "r"(a[2]), "r"(a[3]),
          "r"(b[0]), "r"(b[1]));
}
__device__ __forceinline__ uint32_t pack2h(float a, float b) {
    __half2 h = __floats2half2_rn(a, b);
    return *(uint32_t*)&h;
}
__device__ __forceinline__ void mma_f16(float* c, const uint32_t* a,
                                        uint32_t b0, uint32_t b1) {
    asm volatile(
        "mma.sync.aligned.m16n8k16.row.col.f32.f16.f16.f32 "
        "{%0,%1,%2,%3}, {%4,%5,%6,%7}, {%8,%9}, {%0,%1,%2,%3};\n"
        : "+f"(c[0]), "+f"(c[1]), "+f"(c[2]), "+f"(c[3])
        : "r"(a[0]), "r"(a[1]), "r"(a[2]), "r"(a[3]),
          "r"(b0), "r"(b1));
}
__device__ __forceinline__ void ldsm_x4(uint32_t& r0, uint32_t& r1,
                                        uint32_t& r2, uint32_t& r3,
                                        uint32_t addr) {
    asm volatile(
        "ldmatrix.sync.aligned.m8n8.x4.shared.b16 {%0,%1,%2,%3}, [%4];"
        : "=r"(r0), "=r"(r1), "=r"(r2), "=r"(r3) : "r"(addr));
}
__device__ __forceinline__ void cp16(uint32_t dst, const void* src) {
    asm volatile("cp.async.cg.shared.global [%0], [%1], 16;"
                 :: "r"(dst), "l"(src));
}

// ---------------------------------------------------------------------------
// Kernel 0: convert lin_w -> g_wh (fp16).
// ---------------------------------------------------------------------------
__global__ __launch_bounds__(256) void k0_wh(const float* __restrict__ w)
{
    size_t i = ((size_t)blockIdx.x * 256 + threadIdx.x) * 8;
    float4 a = *(const float4*)(w + i);
    float4 b = *(const float4*)(w + i + 4);
    uint4 u;
    u.x = pack2h(a.x, a.y); u.y = pack2h(a.z, a.w);
    u.z = pack2h(b.x, b.y); u.w = pack2h(b.z, b.w);
    *(uint4*)(g_wh + i) = u;
}

// ---------------------------------------------------------------------------
// Kernel 0b: wq/wk/wv -> fp16 copies. 3 * 25600 elems.
// ---------------------------------------------------------------------------
__global__ __launch_bounds__(256) void k0b_wsmall(
    const float* __restrict__ wq, const float* __restrict__ wk,
    const float* __restrict__ wv)
{
    int gid = blockIdx.x * 256 + threadIdx.x;
    int mat = gid / (EE * EE);
    int i   = gid % (EE * EE);
    if (mat == 0)      g_wqh[i] = __float2half(wq[i]);
    else if (mat == 1) g_wkh[i] = __float2half(wk[i]);
    else               g_wvh[i] = __float2half(wv[i]);
}

// ---------------------------------------------------------------------------
// Kernel 0c: zero the pad columns of g_clp (122 per row). 512*122 = 62464.
// ---------------------------------------------------------------------------
__global__ __launch_bounds__(256) void k0c_zero()
{
    int gid = blockIdx.x * 256 + threadIdx.x;
    if (gid < B_SZ * (2 * PADN)) {
        int b = gid / (2 * PADN), j = gid % (2 * PADN);
        int d = (j < PADN) ? j : (j + DCL);
        g_clp[(size_t)b * DTRF + d] = 0.f;
    }
}

// ---------------------------------------------------------------------------
// Kernel 1: cl = (x*std + mean) @ mat -> g_clp (padded layout)
// ---------------------------------------------------------------------------
__global__ __launch_bounds__(256) void k1_clgemm(
    const float* __restrict__ x, const float* __restrict__ stdv,
    const float* __restrict__ meanv, const float* __restrict__ mat)
{
    __shared__ float u_s[64 * 64];
    const int rbase = blockIdx.y * 64;
    const int cbase = blockIdx.x * 128;
    const int tid = threadIdx.x;

    for (int idx = tid; idx < 64 * 64; idx += 256) {
        int r = idx >> 6, k = idx & 63;
        u_s[idx] = x[(rbase + r) * DIN + k] * stdv[k] + meanv[k];
    }
    __syncthreads();

    const int ty = tid >> 5;
    const int tx = tid & 31;
    int   c[4];  bool cv[4];
#pragma unroll
    for (int j = 0; j < 4; j++) { c[j] = cbase + tx + 32 * j; cv[j] = (c[j] < DCL); }

    float acc[8][4] = {};
    float bcur[2][4], bnxt[2][4];
#pragma unroll
    for (int kk = 0; kk < 2; kk++)
#pragma unroll
        for (int j = 0; j < 4; j++)
            bcur[kk][j] = cv[j] ? mat[kk * DCL + c[j]] : 0.f;

    for (int k = 0; k < 64; k += 2) {
        if (k + 2 < 64) {
#pragma unroll
            for (int kk = 0; kk < 2; kk++)
#pragma unroll
                for (int j = 0; j < 4; j++)
                    bnxt[kk][j] = cv[j] ? mat[(k + 2 + kk) * DCL + c[j]] : 0.f;
        }
#pragma unroll
        for (int kk = 0; kk < 2; kk++) {
            float a[8];
#pragma unroll
            for (int i = 0; i < 8; i++) a[i] = u_s[(ty + 8 * i) * 64 + k + kk];
#pragma unroll
            for (int i = 0; i < 8; i++)
#pragma unroll
                for (int j = 0; j < 4; j++)
                    acc[i][j] += a[i] * bcur[kk][j];
        }
#pragma unroll
        for (int kk = 0; kk < 2; kk++)
#pragma unroll
            for (int j = 0; j < 4; j++)
                bcur[kk][j] = bnxt[kk][j];
    }
#pragma unroll
    for (int i = 0; i < 8; i++) {
        int row = rbase + ty + 8 * i;
#pragma unroll
        for (int j = 0; j < 4; j++)
            if (cv[j]) g_clp[(size_t)row * DTRF + PADN + c[j]] = acc[i][j];
    }
}

// ---------------------------------------------------------------------------
// Kernel 2a: LayerNorm over g_clp (aligned float4) -> g_xnh (fp16).
// 512 blocks x 256 threads.
// ---------------------------------------------------------------------------
__global__ __launch_bounds__(256) void k2a_ln(
    const float* __restrict__ ln_g, const float* __restrict__ ln_b)
{
    __shared__ float red[64];
    const int b = blockIdx.x;
    const int t = threadIdx.x;
    const float4* cl4 = (const float4*)(g_clp + (size_t)b * DTRF);

    float lsum = 0.f, lsq = 0.f;
#pragma unroll
    for (int i = 0; i < 5; i++) {
        float4 v = cl4[t + i * 256];
        lsum += v.x + v.y + v.z + v.w;
        lsq  += v.x * v.x + v.y * v.y + v.z * v.z + v.w * v.w;
    }
#pragma unroll
    for (int o = 16; o > 0; o >>= 1) {
        lsum += __shfl_xor_sync(~0u, lsum, o);
        lsq  += __shfl_xor_sync(~0u, lsq,  o);
    }
    const int warp = t >> 5, lane = t & 31;
    if (lane == 0) { red[warp] = lsum; red[32 + warp] = lsq; }
    __syncthreads();
    if (warp == 0) {
        float a  = (lane < 8) ? red[lane]      : 0.f;
        float c2 = (lane < 8) ? red[32 + lane] : 0.f;
#pragma unroll
        for (int o = 4; o > 0; o >>= 1) {
            a  += __shfl_xor_sync(~0u, a,  o);
            c2 += __shfl_xor_sync(~0u, c2, o);
        }
        if (lane == 0) {
            float mu  = a / (float)DTRF;
            float var = c2 / (float)DTRF - mu * mu;
            red[0] = mu;
            red[1] = rsqrtf(var + 1e-5f);
        }
    }
    __syncthreads();
    const float mu = red[0], rstd = red[1];
    __half* xnrow = g_xnh + (size_t)b * DTRF;
#pragma unroll
    for (int i = 0; i < 5; i++) {
        int i4 = t + i * 256;
        int d  = i4 * 4;
        float4 v  = cl4[i4];
        float4 gg = *(const float4*)&ln_g[d];
        float4 bb = *(const float4*)&ln_b[d];
        uint2 u;
        u.x = pack2h((v.x - mu) * rstd * gg.x + bb.x,
                     (v.y - mu) * rstd * gg.y + bb.y);
        u.y = pack2h((v.z - mu) * rstd * gg.z + bb.z,
                     (v.w - mu) * rstd * gg.w + bb.w);
        *(uint2*)&xnrow[d] = u;
    }
}

// ---------------------------------------------------------------------------
// Kernel 2b: QKV GEMM (fp16 mma), slim. grid (M2/64, 3), 256 threads.
// warps: wm = warp&3 (m16 tile), wn = warp>>2 (N half: 10 n8 tiles).
// smem: Ah[64][168] fp16 (21504 B) + Bs[2][160][24] fp16 (15360 B) = 36864 B
// ---------------------------------------------------------------------------
#define QK_ALD 168
#define QK_BLD 24
__global__ __launch_bounds__(256) void k2b_qkv(
    const float* __restrict__ bq, const float* __restrict__ bk,
    const float* __restrict__ bv)
{
    extern __shared__ __align__(16) __half smb[];
    __half (*Ah)[QK_ALD] = (__half(*)[QK_ALD])smb;
    __half (*Bs)[160][QK_BLD] = (__half(*)[160][QK_BLD])(smb + 64 * QK_ALD);

    const int t    = threadIdx.x;
    const int lane = t & 31;
    const int warp = t >> 5;
    const int wm   = warp & 3;
    const int wn   = warp >> 2;
    const int g    = lane >> 2;
    const int tg   = lane & 3;
    const int rowbase = blockIdx.x * 64;
    const int mat  = blockIdx.y;

    const __half* Wh  = (mat == 0) ? g_wqh : (mat == 1) ? g_wkh : g_wvh;
    const float* bias = (mat == 0) ? bq : (mat == 1) ? bk : bv;
    float*       outp = (mat == 0) ? g_q : (mat == 1) ? g_k : g_v;

    // A tile: 64 rows x 20 chunks = 1280 cp16 (5/thread), uncommitted yet
#pragma unroll
    for (int i = 0; i < 5; i++) {
        int idx = t + i * 256;
        int row = idx / 20, ch = idx % 20;
        uint32_t dst = (uint32_t)__cvta_generic_to_shared(&Ah[row][ch * 8]);
        cp16(dst, g_xnh + (size_t)(rowbase + row) * EE + ch * 8);
    }
    // B chunk loader: 160 rows x 2 half-chunks = 320 cp16
    auto issueB = [&](int kc, int buf) {
#pragma unroll
        for (int i = 0; i < 2; i++) {
            int idx = t + i * 256;
            if (idx < 320) {
                int n = idx >> 1, hf = idx & 1;
                uint32_t dst = (uint32_t)__cvta_generic_to_shared(
                    &Bs[buf][n][hf * 8]);
                cp16(dst, Wh + (size_t)n * EE + kc * 16 + hf * 8);
            }
        }
        asm volatile("cp.async.commit_group;" ::: "memory");
    };
    issueB(0, 0);   // commits A + B0 together

    float acc[10][4] = {};
    for (int kc = 0; kc < 10; kc++) {
        const int buf = kc & 1;
        asm volatile("cp.async.wait_group 0;" ::: "memory");
        __syncthreads();
        if (kc + 1 < 10) issueB(kc + 1, buf ^ 1);

        uint32_t af[4];
        {
            uint32_t addr = (uint32_t)__cvta_generic_to_shared(
                &Ah[wm * 16 + (lane & 15)][kc * 16 + (lane >> 4) * 8]);
            ldsm_x4(af[0], af[1], af[2], af[3], addr);
        }
        uint32_t bf[5][4];
#pragma unroll
        for (int nh = 0; nh < 5; nh++) {
            uint32_t addr = (uint32_t)__cvta_generic_to_shared(
                &Bs[buf][wn * 80 + nh * 16 + (lane & 7) + ((lane >> 4) & 1) * 8]
                   [((lane >> 3) & 1) * 8]);
            ldsm_x4(bf[nh][0], bf[nh][1], bf[nh][2], bf[nh][3], addr);
        }
#pragma unroll
        for (int ni = 0; ni < 10; ni++) {
            const int nh = ni >> 1, sub = ni & 1;
            mma_f16(acc[ni], af, bf[nh][sub * 2], bf[nh][sub * 2 + 1]);
        }
    }

    const int r0 = rowbase + wm * 16 + g;
#pragma unroll
    for (int ni = 0; ni < 10; ni++) {
        const int n0 = wn * 80 + ni * 8 + tg * 2;
        const float bb0 = bias[n0], bb1 = bias[n0 + 1];
        outp[(size_t)r0 * EE + n0]           = acc[ni][0] + bb0;
        outp[(size_t)r0 * EE + n0 + 1]       = acc[ni][1] + bb1;
        outp[(size_t)(r0 + 8) * EE + n0]     = acc[ni][2] + bb0;
        outp[(size_t)(r0 + 8) * EE + n0 + 1] = acc[ni][3] + bb1;
    }
}

// ---------------------------------------------------------------------------
// Kernel 2c: attention per batch row. 512 blocks x 256 threads.
// ---------------------------------------------------------------------------
__global__ __launch_bounds__(256) void k2c_attn()
{
    extern __shared__ float sm2c[];
    float (*sq)[164] = (float(*)[164])sm2c;
    float (*kt)[36]  = (float(*)[36]) (sm2c + 32 * 164);
    float (*sv)[164] = (float(*)[164])(sm2c + 32 * 164 + 160 * 36);
    float (*att)[33] = (float(*)[33]) (sm2c + 64 * 164 + 160 * 36);

    const int b = blockIdx.x;
    const int t = threadIdx.x;
    const float inv_scale = rsqrtf(160.0f);
    const size_t base = (size_t)b * PP * EE;

#pragma unroll
    for (int i = 0; i < 5; i++) {
        int idx = t + i * 256;
        int p = idx / 40, c4 = idx % 40;
        uint32_t dst = (uint32_t)__cvta_generic_to_shared(&sv[p][c4 * 4]);
        cp16(dst, g_v + base + p * EE + c4 * 4);
    }
    asm volatile("cp.async.commit_group;" ::: "memory");

#pragma unroll
    for (int i = 0; i < 5; i++) {
        int idx = t + i * 256;
        int p = idx / 40, c4 = idx % 40;
        float4 qv = *(const float4*)&g_q[base + p * EE + c4 * 4];
        *(float4*)&sq[p][c4 * 4] = make_float4(qv.x * inv_scale, qv.y * inv_scale,
                                               qv.z * inv_scale, qv.w * inv_scale);
        float4 kv = *(const float4*)&g_k[base + p * EE + c4 * 4];
        kt[c4 * 4 + 0][p] = kv.x;
        kt[c4 * 4 + 1][p] = kv.y;
        kt[c4 * 4 + 2][p] = kv.z;
        kt[c4 * 4 + 3][p] = kv.w;
    }
    __syncthreads();

    {
        const int p = t >> 3, q4 = t & 7;
        float a0 = 0.f, a1 = 0.f, a2 = 0.f, a3 = 0.f;
#pragma unroll 4
        for (int e4 = 0; e4 < 40; e4++) {
            float4 qv = *(const float4*)&sq[p][e4 * 4];
            float4 k0 = *(const float4*)&kt[e4 * 4 + 0][q4 * 4];
            float4 k1 = *(const float4*)&kt[e4 * 4 + 1][q4 * 4];
            float4 k2 = *(const float4*)&kt[e4 * 4 + 2][q4 * 4];
            float4 k3 = *(const float4*)&kt[e4 * 4 + 3][q4 * 4];
            a0 += qv.x * k0.x + qv.y * k1.x + qv.z * k2.x + qv.w * k3.x;
            a1 += qv.x * k0.y + qv.y * k1.y + qv.z * k2.y + qv.w * k3.y;
            a2 += qv.x * k0.z + qv.y * k1.z + qv.z * k2.z + qv.w * k3.z;
            a3 += qv.x * k0.w + qv.y * k1.w + qv.z * k2.w + qv.w * k3.w;
        }
        att[p][q4 * 4 + 0] = a0; att[p][q4 * 4 + 1] = a1;
        att[p][q4 * 4 + 2] = a2; att[p][q4 * 4 + 3] = a3;
    }
    __syncthreads();

    if (t < 128) {
        const int q = t >> 2, pg = t & 3;
        float m = -1e30f;
#pragma unroll
        for (int i = 0; i < 8; i++) m = fmaxf(m, att[pg * 8 + i][q]);
        m = fmaxf(m, __shfl_xor_sync(~0u, m, 1));
        m = fmaxf(m, __shfl_xor_sync(~0u, m, 2));
        float s = 0.f;
        float ev[8];
#pragma unroll
        for (int i = 0; i < 8; i++) {
            ev[i] = __expf(att[pg * 8 + i][q] - m);
            s += ev[i];
        }
        s += __shfl_xor_sync(~0u, s, 1);
        s += __shfl_xor_sync(~0u, s, 2);
        float inv = 1.f / s;
#pragma unroll
        for (int i = 0; i < 8; i++) att[pg * 8 + i][q] = ev[i] * inv;
    }
    asm volatile("cp.async.wait_group 0;" ::: "memory");
    __syncthreads();

    const float4* clp4 = (const float4*)(g_clp + (size_t)b * DTRF);
#pragma unroll
    for (int j = 0; j < 5; j++) {
        int idx4 = t + j * 256;
        int p = idx4 / 40, e4 = idx4 % 40;
        float4 a = make_float4(0.f, 0.f, 0.f, 0.f);
#pragma unroll
        for (int q = 0; q < 32; q++) {
            float w = att[p][q];
            float4 vv = *(const float4*)&sv[q][e4 * 4];
            a.x += w * vv.x; a.y += w * vv.y;
            a.z += w * vv.z; a.w += w * vv.w;
        }
        float4 cl = clp4[idx4];
        *(float4*)&g_h[base + idx4 * 4] =
            make_float4(a.x + cl.x, a.y + cl.y, a.z + cl.z, a.w + cl.w);
    }
}

// ---------------------------------------------------------------------------
// Kernel 2d: BT GEMM + Supact + residual (tf32 mma). BM=64, grid 256.
// Writes g_yh (fp16).
// ---------------------------------------------------------------------------
__global__ __launch_bounds__(256) void k2d_bt(
    const float* __restrict__ bt_w, const float* __restrict__ bt_b,
    const float* __restrict__ bt_gain, const float* __restrict__ bt_bias,
    const float* __restrict__ sup_gamma, const float* __restrict__ sup_beta)
{
    extern __shared__ uint32_t sm2d[];
    uint32_t (*As)[164]     = (uint32_t(*)[164])sm2d;
    uint32_t (*Bs)[16][168] = (uint32_t(*)[16][168])(sm2d + 64 * 164);

    const int t    = threadIdx.x;
    const int lane = t & 31;
    const int warp = t >> 5;
    const int wm   = warp & 3;
    const int wn   = warp >> 2;
    const int g    = lane >> 2;
    const int tg   = lane & 3;
    const int mb   = blockIdx.x * 64;
    const float btg = bt_gain[0], btb = bt_bias[0];

    float4 bst[3];
#pragma unroll
    for (int i = 0; i < 3; i++) {
        int idx = t + i * 256;
        if (idx < 640) {
            int e = idx / 40, f4 = idx % 40;
            bst[i] = *(const float4*)&bt_w[(size_t)e * EE + f4 * 4];
        }
    }

    for (int i = t; i < 2560; i += 256) {
        int r = i / 40, c4 = i % 40;
        float4 v = *(const float4*)&g_h[(size_t)(mb + r) * EE + c4 * 4];
        uint4 u = make_uint4(f2tf32(v.x * btg + btb), f2tf32(v.y * btg + btb),
                             f2tf32(v.z * btg + btb), f2tf32(v.w * btg + btb));
        *(uint4*)&As[r][c4 * 4] = u;
    }

    float acc[10][4] = {};
    for (int kc = 0; kc < 10; kc++) {
        const int buf = kc & 1;
#pragma unroll
        for (int i = 0; i < 3; i++) {
            int idx = t + i * 256;
            if (idx < 640) {
                int e = idx / 40, f4 = idx % 40;
                uint4 u = make_uint4(f2tf32(bst[i].x), f2tf32(bst[i].y),
                                     f2tf32(bst[i].z), f2tf32(bst[i].w));
                *(uint4*)&Bs[buf][e][f4 * 4] = u;
            }
        }
        __syncthreads();
        if (kc + 1 < 10) {
            int k0 = (kc + 1) * 16;
#pragma unroll
            for (int i = 0; i < 3; i++) {
                int idx = t + i * 256;
                if (idx < 640) {
                    int e = idx / 40, f4 = idx % 40;
                    bst[i] = *(const float4*)&bt_w[(size_t)(k0 + e) * EE + f4 * 4];
                }
            }
        }
#pragma unroll
        for (int ks = 0; ks < 2; ks++) {
            const int kA = kc * 16 + ks * 8;
            uint32_t af[4];
            af[0] = As[wm * 16 + g][kA + tg];
            af[1] = As[wm * 16 + g + 8][kA + tg];
            af[2] = As[wm * 16 + g][kA + tg + 4];
            af[3] = As[wm * 16 + g + 8][kA + tg + 4];
#pragma unroll
            for (int j = 0; j < 10; j++) {
                const int n8 = wn * 10 + j;
                uint32_t bf[2];
                bf[0] = Bs[buf][ks * 8 + tg][n8 * 8 + g];
                bf[1] = Bs[buf][ks * 8 + tg + 4][n8 * 8 + g];
                mma_tf32(acc[j], af, bf);
            }
        }
    }

    const int r0 = mb + wm * 16 + g;
#pragma unroll
    for (int j = 0; j < 10; j++) {
        const int n0 = (wn * 10 + j) * 8 + tg * 2;
        const float bb0 = bt_b[n0], bb1 = bt_b[n0 + 1];
#pragma unroll
        for (int half = 0; half < 2; half++) {
            const int row = r0 + half * 8;
            const int gi0 = (row & 31) * EE + n0;
            float o0 = acc[j][half * 2 + 0] + bb0;
            float o1 = acc[j][half * 2 + 1] + bb1;
            float gm0 = sup_gamma[gi0],     gm1 = sup_gamma[gi0 + 1];
            float sb0 = sup_beta[gi0],      sb1 = sup_beta[gi0 + 1];
            float h0  = g_h[(size_t)row * EE + n0];
            float h1  = g_h[(size_t)row * EE + n0 + 1];
            float s0 = 1.f / (1.f + __expf(-sb0 * o0));
            float s1 = 1.f / (1.f + __expf(-sb1 * o1));
            float y0 = (gm0 + s0 * (1.f - gm0)) * o0 + h0;
            float y1 = (gm1 + s1 * (1.f - gm1)) * o1 + h1;
            *(__half2*)&g_yh[(size_t)row * EE + n0] = __floats2half2_rn(y0, y1);
        }
    }
}

// ---------------------------------------------------------------------------
// Kernel 3: z = y @ lin_w^T  (fp16 in, cp.async double-buffered, ldmatrix)
// BM=128, BN=96, BK=64, 256 threads, grid (32,4)=128 CTAs — ONE wave.
// ---------------------------------------------------------------------------
#define K3_BM 128
#define K3_BN 96
#define K3_BK 64
#define K3_LDH 72
#define K3_NIT (DTRF / K3_BK)    // 80
#define K3_A_OFF(buf) ((buf) * K3_BM * K3_LDH)
#define K3_B_OFF(buf) (2 * K3_BM * K3_LDH + (buf) * K3_BN * K3_LDH)
#define K3_SMEM ((2 * K3_BM * K3_LDH + 2 * K3_BN * K3_LDH) * 2)   // 64512 B

__global__ __launch_bounds__(256) void k3_f16(
    const float* __restrict__ lin_b,
    const float* __restrict__ og_p, const float* __restrict__ ob_p,
    float* __restrict__ out)
{
    extern __shared__ __align__(16) __half smh[];
    const uint32_t sbase = (uint32_t)__cvta_generic_to_shared(smh);

    const int t    = threadIdx.x;
    const int lane = t & 31;
    const int warp = t >> 5;
    const int wm   = warp >> 1;
    const int wn   = warp & 1;
    const int g    = lane >> 2;
    const int tg   = lane & 3;

    const int mbase = blockIdx.y * K3_BM;
    const int nbase = blockIdx.x * K3_BN;

    const int arow0 = t >> 3;
    const int ach   = t & 7;

    float acc[2][6][4] = {};

    auto issue = [&](int it, int buf) {
        const int kh = it * K3_BK;
#pragma unroll
        for (int i = 0; i < 4; i++) {
            int row = arow0 + i * 32;
            uint32_t dst = sbase +
                (uint32_t)(K3_A_OFF(buf) + row * K3_LDH + ach * 8) * 2;
            cp16(dst, g_yh + (size_t)(mbase + row) * DTRF + kh + ach * 8);
        }
#pragma unroll
        for (int i = 0; i < 3; i++) {
            int row = arow0 + i * 32;
            int br = nbase + row;
            if (br >= DOUT) br = 0;
            uint32_t dst = sbase +
                (uint32_t)(K3_B_OFF(buf) + row * K3_LDH + ach * 8) * 2;
            cp16(dst, g_wh + (size_t)br * DTRF + kh + ach * 8);
        }
        asm volatile("cp.async.commit_group;" ::: "memory");
    };

    issue(0, 0);

    for (int it = 0; it < K3_NIT; it++) {
        const int buf = it & 1;
        asm volatile("cp.async.wait_group 0;" ::: "memory");
        __syncthreads();
        if (it + 1 < K3_NIT) issue(it + 1, buf ^ 1);

#pragma unroll
        for (int ks = 0; ks < 4; ks++) {
            const int k0 = ks * 16;
            uint32_t af[2][4];
#pragma unroll
            for (int mi = 0; mi < 2; mi++) {
                const int rb = wm * 32 + mi * 16;
                uint32_t addr = sbase + (uint32_t)(K3_A_OFF(buf) +
                    (rb + (lane & 15)) * K3_LDH + k0 + (lane >> 4) * 8) * 2;
                ldsm_x4(af[mi][0], af[mi][1], af[mi][2], af[mi][3], addr);
            }
            uint32_t bf[3][4];
#pragma unroll
            for (int nh = 0; nh < 3; nh++) {
                const int nb = wn * 48 + nh * 16;
                uint32_t addr = sbase + (uint32_t)(K3_B_OFF(buf) +
                    (nb + (lane & 7) + ((lane >> 4) & 1) * 8) * K3_LDH +
                    k0 + ((lane >> 3) & 1) * 8) * 2;
                ldsm_x4(bf[nh][0], bf[nh][1], bf[nh][2], bf[nh][3], addr);
            }
#pragma unroll
            for (int mi = 0; mi < 2; mi++)
#pragma unroll
                for (int ni = 0; ni < 6; ni++) {
                    const int nh = ni >> 1, sub = ni & 1;
                    mma_f16(acc[mi][ni], af[mi],
                            bf[nh][sub * 2], bf[nh][sub * 2 + 1]);
                }
        }
    }

    const float og = og_p[0], ob = ob_p[0];
#pragma unroll
    for (int mi = 0; mi < 2; mi++) {
        const int m0 = mbase + wm * 32 + mi * 16 + g;
#pragma unroll
        for (int ni = 0; ni < 6; ni++) {
            const int n0 = nbase + wn * 48 + ni * 8 + tg * 2;
            if (n0 + 1 < DOUT) {
                const float lb0 = lin_b[n0], lb1 = lin_b[n0 + 1];
                out[(size_t)m0 * DOUT + n0]           = (acc[mi][ni][0] + lb0) * og + ob;
                out[(size_t)m0 * DOUT + n0 + 1]       = (acc[mi][ni][1] + lb1) * og + ob;
                out[(size_t)(m0 + 8) * DOUT + n0]     = (acc[mi][ni][2] + lb0) * og + ob;
                out[(size_t)(m0 + 8) * DOUT + n0 + 1] = (acc[mi][ni][3] + lb1) * og + ob;
            } else if (n0 < DOUT) {
                const float lb0 = lin_b[n0];
                out[(size_t)m0 * DOUT + n0]       = (acc[mi][ni][0] + lb0) * og + ob;
                out[(size_t)(m0 + 8) * DOUT + n0] = (acc[mi][ni][2] + lb0) * og + ob;
            }
        }
    }
}

// ---------------------------------------------------------------------------
extern "C" void kernel_launch(void* const* d_in, const int* in_sizes, int n_in,
                              void* d_out, int out_size)
{
    const float* x         = (const float*)d_in[0];
    const float* stdv      = (const float*)d_in[1];
    const float* meanv     = (const float*)d_in[2];
    const float* mat       = (const float*)d_in[3];
    const float* ln_g      = (const float*)d_in[4];
    const float* ln_b      = (const float*)d_in[5];
    const float* wq        = (const float*)d_in[6];
    const float* bq        = (const float*)d_in[7];
    const float* wk        = (const float*)d_in[8];
    const float* bk        = (const float*)d_in[9];
    const float* wv        = (const float*)d_in[10];
    const float* bv        = (const float*)d_in[11];
    const float* bt_w      = (const float*)d_in[12];
    const float* bt_b      = (const float*)d_in[13];
    const float* bt_gain   = (const float*)d_in[14];
    const float* bt_bias   = (const float*)d_in[15];
    const float* sup_gamma = (const float*)d_in[16];
    const float* sup_beta  = (const float*)d_in[17];
    const float* lin_w     = (const float*)d_in[18];
    const float* lin_b     = (const float*)d_in[19];
    const float* out_gain  = (const float*)d_in[20];
    const float* out_bias  = (const float*)d_in[21];
    float* out = (float*)d_out;

    const int smem2b = (64 * QK_ALD + 2 * 160 * QK_BLD) * 2;           // 36864
    const int smem2c = (64 * 164 + 160 * 36 + 32 * 33) * 4;            // 69248
    const int smem2d = (64 * 164 + 2 * 16 * 168) * 4;                  // 63488

    cudaFuncSetAttribute(k2b_qkv, cudaFuncAttributeMaxDynamicSharedMemorySize, smem2b);
    cudaFuncSetAttribute(k2c_attn, cudaFuncAttributeMaxDynamicSharedMemorySize, smem2c);
    cudaFuncSetAttribute(k2d_bt,  cudaFuncAttributeMaxDynamicSharedMemorySize, smem2d);
    cudaFuncSetAttribute(k3_f16,  cudaFuncAttributeMaxDynamicSharedMemorySize, K3_SMEM);

    k0_wh    <<<DOUT * DTRF / (8 * 256), 256>>>(lin_w);
    k0b_wsmall<<<3 * EE * EE / 256, 256>>>(wq, wk, wv);
    k0c_zero <<<(B_SZ * 2 * PADN + 255) / 256, 256>>>();
    k1_clgemm<<<dim3(40, 8), 256>>>(x, stdv, meanv, mat);
    k2a_ln   <<<B_SZ, 256>>>(ln_g, ln_b);
    k2b_qkv  <<<dim3(M2 / 64, 3), 256, smem2b>>>(bq, bk, bv);
    k2c_attn <<<B_SZ, 256, smem2c>>>();
    k2d_bt   <<<M2 / 64, 256, smem2d>>>(bt_w, bt_b, bt_gain, bt_bias,
                                        sup_gamma, sup_beta);
    k3_f16   <<<dim3((DOUT + K3_BN - 1) / K3_BN, B_SZ / K3_BM), 256, K3_SMEM>>>(
        lin_b, out_gain, out_bias, out);
}

// round 17
// speedup vs baseline: 1.0776x; 1.0365x over previous
#include <cuda_runtime.h>
#include <cuda_fp16.h>
#include <math.h>
#include <stdint.h>

// Problem constants
#define B_SZ  512
#define DIN   64
#define DCL   4998
#define DTRF  5120
#define PADN  61
#define PP    32
#define EE    160
#define DOUT  3000
#define M2    (B_SZ * PP)          // 16384 rows of 160

// Global scratch
__device__ __align__(256) float g_clp[B_SZ * DTRF];    // padded cl (zeros in pads)
__device__ float g_q [M2 * EE];
__device__ float g_k [M2 * EE];
__device__ float g_v [M2 * EE];
__device__ float g_h [M2 * EE];
__device__ __align__(256) __half g_xnh[M2 * EE];       // LN output fp16
__device__ __align__(256) __half g_yh[M2 * EE];        // y fp16 (k3 A)
__device__ __align__(256) __half g_wh[DOUT * DTRF];    // lin_w fp16 (k3 B)
__device__ __align__(256) __half g_wqh[EE * EE];
__device__ __align__(256) __half g_wkh[EE * EE];
__device__ __align__(256) __half g_wvh[EE * EE];

// ---------------------------------------------------------------------------
// helpers
// ---------------------------------------------------------------------------
__device__ __forceinline__ uint32_t f2tf32(float f) {
    uint32_t u;
    asm("cvt.rna.tf32.f32 %0, %1;" : "=r"(u) : "f"(f));
    return u;
}
__device__ __forceinline__ void mma_tf32(float* c, const uint32_t* a,
                                         const uint32_t* b) {
    asm volatile(
        "mma.sync.aligned.m16n8k8.row.col.f32.tf32.tf32.f32 "
        "{%0,%1,%2,%3}, {%4,%5,%6,%7}, {%8,%9}, {%0,%1,%2,%3};\n"
        : "+f"(c[0]), "+f"(c[1]), "+f"(c[2]), "+f"(c[3])
        : "r"(a[0]), "r"(a[1]), "r"(a[2]), "r"(a[3]),
          "r"(b[0]), "r"(b[1]));
}
__device__ __forceinline__ uint32_t pack2h(float a, float b) {
    __half2 h = __floats2half2_rn(a, b);
    return *(uint32_t*)&h;
}
__device__ __forceinline__ void mma_f16(float* c, const uint32_t* a,
                                        uint32_t b0, uint32_t b1) {
    asm volatile(
        "mma.sync.aligned.m16n8k16.row.col.f32.f16.f16.f32 "
        "{%0,%1,%2,%3}, {%4,%5,%6,%7}, {%8,%9}, {%0,%1,%2,%3};\n"
        : "+f"(c[0]), "+f"(c[1]), "+f"(c[2]), "+f"(c[3])
        : "r"(a[0]), "r"(a[1]), "r"(a[2]), "r"(a[3]),
          "r"(b0), "r"(b1));
}
__device__ __forceinline__ void ldsm_x4(uint32_t& r0, uint32_t& r1,
                                        uint32_t& r2, uint32_t& r3,
                                        uint32_t addr) {
    asm volatile(
        "ldmatrix.sync.aligned.m8n8.x4.shared.b16 {%0,%1,%2,%3}, [%4];"
        : "=r"(r0), "=r"(r1), "=r"(r2), "=r"(r3) : "r"(addr));
}
__device__ __forceinline__ void cp16(uint32_t dst, const void* src) {
    asm volatile("cp.async.cg.shared.global [%0], [%1], 16;"
                 :: "r"(dst), "l"(src));
}

// ---------------------------------------------------------------------------
// Kernel 0: convert lin_w -> g_wh (fp16).
// ---------------------------------------------------------------------------
__global__ __launch_bounds__(256) void k0_wh(const float* __restrict__ w)
{
    size_t i = ((size_t)blockIdx.x * 256 + threadIdx.x) * 8;
    float4 a = *(const float4*)(w + i);
    float4 b = *(const float4*)(w + i + 4);
    uint4 u;
    u.x = pack2h(a.x, a.y); u.y = pack2h(a.z, a.w);
    u.z = pack2h(b.x, b.y); u.w = pack2h(b.z, b.w);
    *(uint4*)(g_wh + i) = u;
}

// ---------------------------------------------------------------------------
// Kernel 0b: wq/wk/wv -> fp16 copies. 3 * 25600 elems.
// ---------------------------------------------------------------------------
__global__ __launch_bounds__(256) void k0b_wsmall(
    const float* __restrict__ wq, const float* __restrict__ wk,
    const float* __restrict__ wv)
{
    int gid = blockIdx.x * 256 + threadIdx.x;
    int mat = gid / (EE * EE);
    int i   = gid % (EE * EE);
    if (mat == 0)      g_wqh[i] = __float2half(wq[i]);
    else if (mat == 1) g_wkh[i] = __float2half(wk[i]);
    else               g_wvh[i] = __float2half(wv[i]);
}

// ---------------------------------------------------------------------------
// Kernel 0c: zero the pad columns of g_clp (122 per row). 512*122 = 62464.
// ---------------------------------------------------------------------------
__global__ __launch_bounds__(256) void k0c_zero()
{
    int gid = blockIdx.x * 256 + threadIdx.x;
    if (gid < B_SZ * (2 * PADN)) {
        int b = gid / (2 * PADN), j = gid % (2 * PADN);
        int d = (j < PADN) ? j : (j + DCL);
        g_clp[(size_t)b * DTRF + d] = 0.f;
    }
}

// ---------------------------------------------------------------------------
// Kernel 1: cl = (x*std + mean) @ mat -> g_clp (padded layout)
// 32x128 tile, 4x4 per thread, depth-4 mat prefetch (MLP 16). Grid 40x16.
// ---------------------------------------------------------------------------
__global__ __launch_bounds__(256) void k1_clgemm(
    const float* __restrict__ x, const float* __restrict__ stdv,
    const float* __restrict__ meanv, const float* __restrict__ mat)
{
    __shared__ float u_s[32 * 64];
    const int rbase = blockIdx.y * 32;
    const int cbase = blockIdx.x * 128;
    const int tid = threadIdx.x;

    for (int idx = tid; idx < 32 * 64; idx += 256) {
        int r = idx >> 6, k = idx & 63;
        u_s[idx] = x[(rbase + r) * DIN + k] * stdv[k] + meanv[k];
    }
    __syncthreads();

    const int ty = tid >> 5;   // 0..7
    const int tx = tid & 31;
    int   c[4];  bool cv[4];
#pragma unroll
    for (int j = 0; j < 4; j++) { c[j] = cbase + tx + 32 * j; cv[j] = (c[j] < DCL); }

    float acc[4][4] = {};
    float bcur[4][4], bnxt[4][4];
#pragma unroll
    for (int kk = 0; kk < 4; kk++)
#pragma unroll
        for (int j = 0; j < 4; j++)
            bcur[kk][j] = cv[j] ? mat[kk * DCL + c[j]] : 0.f;

    for (int k = 0; k < 64; k += 4) {
        if (k + 4 < 64) {
#pragma unroll
            for (int kk = 0; kk < 4; kk++)
#pragma unroll
                for (int j = 0; j < 4; j++)
                    bnxt[kk][j] = cv[j] ? mat[(k + 4 + kk) * DCL + c[j]] : 0.f;
        }
#pragma unroll
        for (int kk = 0; kk < 4; kk++) {
            float a[4];
#pragma unroll
            for (int i = 0; i < 4; i++) a[i] = u_s[(ty + 8 * i) * 64 + k + kk];
#pragma unroll
            for (int i = 0; i < 4; i++)
#pragma unroll
                for (int j = 0; j < 4; j++)
                    acc[i][j] += a[i] * bcur[kk][j];
        }
#pragma unroll
        for (int kk = 0; kk < 4; kk++)
#pragma unroll
            for (int j = 0; j < 4; j++)
                bcur[kk][j] = bnxt[kk][j];
    }
#pragma unroll
    for (int i = 0; i < 4; i++) {
        int row = rbase + ty + 8 * i;
#pragma unroll
        for (int j = 0; j < 4; j++)
            if (cv[j]) g_clp[(size_t)row * DTRF + PADN + c[j]] = acc[i][j];
    }
}

// ---------------------------------------------------------------------------
// Kernel 2a: LayerNorm over g_clp (aligned float4) -> g_xnh (fp16).
// ---------------------------------------------------------------------------
__global__ __launch_bounds__(256) void k2a_ln(
    const float* __restrict__ ln_g, const float* __restrict__ ln_b)
{
    __shared__ float red[64];
    const int b = blockIdx.x;
    const int t = threadIdx.x;
    const float4* cl4 = (const float4*)(g_clp + (size_t)b * DTRF);

    float lsum = 0.f, lsq = 0.f;
#pragma unroll
    for (int i = 0; i < 5; i++) {
        float4 v = cl4[t + i * 256];
        lsum += v.x + v.y + v.z + v.w;
        lsq  += v.x * v.x + v.y * v.y + v.z * v.z + v.w * v.w;
    }
#pragma unroll
    for (int o = 16; o > 0; o >>= 1) {
        lsum += __shfl_xor_sync(~0u, lsum, o);
        lsq  += __shfl_xor_sync(~0u, lsq,  o);
    }
    const int warp = t >> 5, lane = t & 31;
    if (lane == 0) { red[warp] = lsum; red[32 + warp] = lsq; }
    __syncthreads();
    if (warp == 0) {
        float a  = (lane < 8) ? red[lane]      : 0.f;
        float c2 = (lane < 8) ? red[32 + lane] : 0.f;
#pragma unroll
        for (int o = 4; o > 0; o >>= 1) {
            a  += __shfl_xor_sync(~0u, a,  o);
            c2 += __shfl_xor_sync(~0u, c2, o);
        }
        if (lane == 0) {
            float mu  = a / (float)DTRF;
            float var = c2 / (float)DTRF - mu * mu;
            red[0] = mu;
            red[1] = rsqrtf(var + 1e-5f);
        }
    }
    __syncthreads();
    const float mu = red[0], rstd = red[1];
    __half* xnrow = g_xnh + (size_t)b * DTRF;
#pragma unroll
    for (int i = 0; i < 5; i++) {
        int i4 = t + i * 256;
        int d  = i4 * 4;
        float4 v  = cl4[i4];
        float4 gg = *(const float4*)&ln_g[d];
        float4 bb = *(const float4*)&ln_b[d];
        uint2 u;
        u.x = pack2h((v.x - mu) * rstd * gg.x + bb.x,
                     (v.y - mu) * rstd * gg.y + bb.y);
        u.y = pack2h((v.z - mu) * rstd * gg.z + bb.z,
                     (v.w - mu) * rstd * gg.w + bb.w);
        *(uint2*)&xnrow[d] = u;
    }
}

// ---------------------------------------------------------------------------
// Kernel 2b: QKV GEMM (fp16 mma), slim. grid (M2/64, 3), 256 threads.
// ---------------------------------------------------------------------------
#define QK_ALD 168
#define QK_BLD 24
__global__ __launch_bounds__(256) void k2b_qkv(
    const float* __restrict__ bq, const float* __restrict__ bk,
    const float* __restrict__ bv)
{
    extern __shared__ __align__(16) __half smb[];
    __half (*Ah)[QK_ALD] = (__half(*)[QK_ALD])smb;
    __half (*Bs)[160][QK_BLD] = (__half(*)[160][QK_BLD])(smb + 64 * QK_ALD);

    const int t    = threadIdx.x;
    const int lane = t & 31;
    const int warp = t >> 5;
    const int wm   = warp & 3;
    const int wn   = warp >> 2;
    const int g    = lane >> 2;
    const int tg   = lane & 3;
    const int rowbase = blockIdx.x * 64;
    const int mat  = blockIdx.y;

    const __half* Wh  = (mat == 0) ? g_wqh : (mat == 1) ? g_wkh : g_wvh;
    const float* bias = (mat == 0) ? bq : (mat == 1) ? bk : bv;
    float*       outp = (mat == 0) ? g_q : (mat == 1) ? g_k : g_v;

#pragma unroll
    for (int i = 0; i < 5; i++) {
        int idx = t + i * 256;
        int row = idx / 20, ch = idx % 20;
        uint32_t dst = (uint32_t)__cvta_generic_to_shared(&Ah[row][ch * 8]);
        cp16(dst, g_xnh + (size_t)(rowbase + row) * EE + ch * 8);
    }
    auto issueB = [&](int kc, int buf) {
#pragma unroll
        for (int i = 0; i < 2; i++) {
            int idx = t + i * 256;
            if (idx < 320) {
                int n = idx >> 1, hf = idx & 1;
                uint32_t dst = (uint32_t)__cvta_generic_to_shared(
                    &Bs[buf][n][hf * 8]);
                cp16(dst, Wh + (size_t)n * EE + kc * 16 + hf * 8);
            }
        }
        asm volatile("cp.async.commit_group;" ::: "memory");
    };
    issueB(0, 0);

    float acc[10][4] = {};
    for (int kc = 0; kc < 10; kc++) {
        const int buf = kc & 1;
        asm volatile("cp.async.wait_group 0;" ::: "memory");
        __syncthreads();
        if (kc + 1 < 10) issueB(kc + 1, buf ^ 1);

        uint32_t af[4];
        {
            uint32_t addr = (uint32_t)__cvta_generic_to_shared(
                &Ah[wm * 16 + (lane & 15)][kc * 16 + (lane >> 4) * 8]);
            ldsm_x4(af[0], af[1], af[2], af[3], addr);
        }
        uint32_t bf[5][4];
#pragma unroll
        for (int nh = 0; nh < 5; nh++) {
            uint32_t addr = (uint32_t)__cvta_generic_to_shared(
                &Bs[buf][wn * 80 + nh * 16 + (lane & 7) + ((lane >> 4) & 1) * 8]
                   [((lane >> 3) & 1) * 8]);
            ldsm_x4(bf[nh][0], bf[nh][1], bf[nh][2], bf[nh][3], addr);
        }
#pragma unroll
        for (int ni = 0; ni < 10; ni++) {
            const int nh = ni >> 1, sub = ni & 1;
            mma_f16(acc[ni], af, bf[nh][sub * 2], bf[nh][sub * 2 + 1]);
        }
    }

    const int r0 = rowbase + wm * 16 + g;
#pragma unroll
    for (int ni = 0; ni < 10; ni++) {
        const int n0 = wn * 80 + ni * 8 + tg * 2;
        const float bb0 = bias[n0], bb1 = bias[n0 + 1];
        outp[(size_t)r0 * EE + n0]           = acc[ni][0] + bb0;
        outp[(size_t)r0 * EE + n0 + 1]       = acc[ni][1] + bb1;
        outp[(size_t)(r0 + 8) * EE + n0]     = acc[ni][2] + bb0;
        outp[(size_t)(r0 + 8) * EE + n0 + 1] = acc[ni][3] + bb1;
    }
}

// ---------------------------------------------------------------------------
// Kernel 2c: attention per batch row. 512 blocks x 256 threads.
// ---------------------------------------------------------------------------
__global__ __launch_bounds__(256) void k2c_attn()
{
    extern __shared__ float sm2c[];
    float (*sq)[164] = (float(*)[164])sm2c;
    float (*kt)[36]  = (float(*)[36]) (sm2c + 32 * 164);
    float (*sv)[164] = (float(*)[164])(sm2c + 32 * 164 + 160 * 36);
    float (*att)[33] = (float(*)[33]) (sm2c + 64 * 164 + 160 * 36);

    const int b = blockIdx.x;
    const int t = threadIdx.x;
    const float inv_scale = rsqrtf(160.0f);
    const size_t base = (size_t)b * PP * EE;

#pragma unroll
    for (int i = 0; i < 5; i++) {
        int idx = t + i * 256;
        int p = idx / 40, c4 = idx % 40;
        uint32_t dst = (uint32_t)__cvta_generic_to_shared(&sv[p][c4 * 4]);
        cp16(dst, g_v + base + p * EE + c4 * 4);
    }
    asm volatile("cp.async.commit_group;" ::: "memory");

#pragma unroll
    for (int i = 0; i < 5; i++) {
        int idx = t + i * 256;
        int p = idx / 40, c4 = idx % 40;
        float4 qv = *(const float4*)&g_q[base + p * EE + c4 * 4];
        *(float4*)&sq[p][c4 * 4] = make_float4(qv.x * inv_scale, qv.y * inv_scale,
                                               qv.z * inv_scale, qv.w * inv_scale);
        float4 kv = *(const float4*)&g_k[base + p * EE + c4 * 4];
        kt[c4 * 4 + 0][p] = kv.x;
        kt[c4 * 4 + 1][p] = kv.y;
        kt[c4 * 4 + 2][p] = kv.z;
        kt[c4 * 4 + 3][p] = kv.w;
    }
    __syncthreads();

    {
        const int p = t >> 3, q4 = t & 7;
        float a0 = 0.f, a1 = 0.f, a2 = 0.f, a3 = 0.f;
#pragma unroll 4
        for (int e4 = 0; e4 < 40; e4++) {
            float4 qv = *(const float4*)&sq[p][e4 * 4];
            float4 k0 = *(const float4*)&kt[e4 * 4 + 0][q4 * 4];
            float4 k1 = *(const float4*)&kt[e4 * 4 + 1][q4 * 4];
            float4 k2 = *(const float4*)&kt[e4 * 4 + 2][q4 * 4];
            float4 k3 = *(const float4*)&kt[e4 * 4 + 3][q4 * 4];
            a0 += qv.x * k0.x + qv.y * k1.x + qv.z * k2.x + qv.w * k3.x;
            a1 += qv.x * k0.y + qv.y * k1.y + qv.z * k2.y + qv.w * k3.y;
            a2 += qv.x * k0.z + qv.y * k1.z + qv.z * k2.z + qv.w * k3.z;
            a3 += qv.x * k0.w + qv.y * k1.w + qv.z * k2.w + qv.w * k3.w;
        }
        att[p][q4 * 4 + 0] = a0; att[p][q4 * 4 + 1] = a1;
        att[p][q4 * 4 + 2] = a2; att[p][q4 * 4 + 3] = a3;
    }
    __syncthreads();

    if (t < 128) {
        const int q = t >> 2, pg = t & 3;
        float m = -1e30f;
#pragma unroll
        for (int i = 0; i < 8; i++) m = fmaxf(m, att[pg * 8 + i][q]);
        m = fmaxf(m, __shfl_xor_sync(~0u, m, 1));
        m = fmaxf(m, __shfl_xor_sync(~0u, m, 2));
        float s = 0.f;
        float ev[8];
#pragma unroll
        for (int i = 0; i < 8; i++) {
            ev[i] = __expf(att[pg * 8 + i][q] - m);
            s += ev[i];
        }
        s += __shfl_xor_sync(~0u, s, 1);
        s += __shfl_xor_sync(~0u, s, 2);
        float inv = 1.f / s;
#pragma unroll
        for (int i = 0; i < 8; i++) att[pg * 8 + i][q] = ev[i] * inv;
    }
    asm volatile("cp.async.wait_group 0;" ::: "memory");
    __syncthreads();

    const float4* clp4 = (const float4*)(g_clp + (size_t)b * DTRF);
#pragma unroll
    for (int j = 0; j < 5; j++) {
        int idx4 = t + j * 256;
        int p = idx4 / 40, e4 = idx4 % 40;
        float4 a = make_float4(0.f, 0.f, 0.f, 0.f);
#pragma unroll
        for (int q = 0; q < 32; q++) {
            float w = att[p][q];
            float4 vv = *(const float4*)&sv[q][e4 * 4];
            a.x += w * vv.x; a.y += w * vv.y;
            a.z += w * vv.z; a.w += w * vv.w;
        }
        float4 cl = clp4[idx4];
        *(float4*)&g_h[base + idx4 * 4] =
            make_float4(a.x + cl.x, a.y + cl.y, a.z + cl.z, a.w + cl.w);
    }
}

// ---------------------------------------------------------------------------
// Kernel 2d: BT GEMM + Supact + residual (tf32 mma). BM=64, grid 256.
// Writes g_yh (fp16).
// ---------------------------------------------------------------------------
__global__ __launch_bounds__(256) void k2d_bt(
    const float* __restrict__ bt_w, const float* __restrict__ bt_b,
    const float* __restrict__ bt_gain, const float* __restrict__ bt_bias,
    const float* __restrict__ sup_gamma, const float* __restrict__ sup_beta)
{
    extern __shared__ uint32_t sm2d[];
    uint32_t (*As)[164]     = (uint32_t(*)[164])sm2d;
    uint32_t (*Bs)[16][168] = (uint32_t(*)[16][168])(sm2d + 64 * 164);

    const int t    = threadIdx.x;
    const int lane = t & 31;
    const int warp = t >> 5;
    const int wm   = warp & 3;
    const int wn   = warp >> 2;
    const int g    = lane >> 2;
    const int tg   = lane & 3;
    const int mb   = blockIdx.x * 64;
    const float btg = bt_gain[0], btb = bt_bias[0];

    float4 bst[3];
#pragma unroll
    for (int i = 0; i < 3; i++) {
        int idx = t + i * 256;
        if (idx < 640) {
            int e = idx / 40, f4 = idx % 40;
            bst[i] = *(const float4*)&bt_w[(size_t)e * EE + f4 * 4];
        }
    }

    for (int i = t; i < 2560; i += 256) {
        int r = i / 40, c4 = i % 40;
        float4 v = *(const float4*)&g_h[(size_t)(mb + r) * EE + c4 * 4];
        uint4 u = make_uint4(f2tf32(v.x * btg + btb), f2tf32(v.y * btg + btb),
                             f2tf32(v.z * btg + btb), f2tf32(v.w * btg + btb));
        *(uint4*)&As[r][c4 * 4] = u;
    }

    float acc[10][4] = {};
    for (int kc = 0; kc < 10; kc++) {
        const int buf = kc & 1;
#pragma unroll
        for (int i = 0; i < 3; i++) {
            int idx = t + i * 256;
            if (idx < 640) {
                int e = idx / 40, f4 = idx % 40;
                uint4 u = make_uint4(f2tf32(bst[i].x), f2tf32(bst[i].y),
                                     f2tf32(bst[i].z), f2tf32(bst[i].w));
                *(uint4*)&Bs[buf][e][f4 * 4] = u;
            }
        }
        __syncthreads();
        if (kc + 1 < 10) {
            int k0 = (kc + 1) * 16;
#pragma unroll
            for (int i = 0; i < 3; i++) {
                int idx = t + i * 256;
                if (idx < 640) {
                    int e = idx / 40, f4 = idx % 40;
                    bst[i] = *(const float4*)&bt_w[(size_t)(k0 + e) * EE + f4 * 4];
                }
            }
        }
#pragma unroll
        for (int ks = 0; ks < 2; ks++) {
            const int kA = kc * 16 + ks * 8;
            uint32_t af[4];
            af[0] = As[wm * 16 + g][kA + tg];
            af[1] = As[wm * 16 + g + 8][kA + tg];
            af[2] = As[wm * 16 + g][kA + tg + 4];
            af[3] = As[wm * 16 + g + 8][kA + tg + 4];
#pragma unroll
            for (int j = 0; j < 10; j++) {
                const int n8 = wn * 10 + j;
                uint32_t bf[2];
                bf[0] = Bs[buf][ks * 8 + tg][n8 * 8 + g];
                bf[1] = Bs[buf][ks * 8 + tg + 4][n8 * 8 + g];
                mma_tf32(acc[j], af, bf);
            }
        }
    }

    const int r0 = mb + wm * 16 + g;
#pragma unroll
    for (int j = 0; j < 10; j++) {
        const int n0 = (wn * 10 + j) * 8 + tg * 2;
        const float bb0 = bt_b[n0], bb1 = bt_b[n0 + 1];
#pragma unroll
        for (int half = 0; half < 2; half++) {
            const int row = r0 + half * 8;
            const int gi0 = (row & 31) * EE + n0;
            float o0 = acc[j][half * 2 + 0] + bb0;
            float o1 = acc[j][half * 2 + 1] + bb1;
            float gm0 = sup_gamma[gi0],     gm1 = sup_gamma[gi0 + 1];
            float sb0 = sup_beta[gi0],      sb1 = sup_beta[gi0 + 1];
            float h0  = g_h[(size_t)row * EE + n0];
            float h1  = g_h[(size_t)row * EE + n0 + 1];
            float s0 = 1.f / (1.f + __expf(-sb0 * o0));
            float s1 = 1.f / (1.f + __expf(-sb1 * o1));
            float y0 = (gm0 + s0 * (1.f - gm0)) * o0 + h0;
            float y1 = (gm1 + s1 * (1.f - gm1)) * o1 + h1;
            *(__half2*)&g_yh[(size_t)row * EE + n0] = __floats2half2_rn(y0, y1);
        }
    }
}

// ---------------------------------------------------------------------------
// Kernel 3: z = y @ lin_w^T  (fp16 in, cp.async double-buffered, ldmatrix)
// BM=128, BN=96, BK=64, 256 threads, grid (32,4)=128 CTAs — ONE wave.
// ---------------------------------------------------------------------------
#define K3_BM 128
#define K3_BN 96
#define K3_BK 64
#define K3_LDH 72
#define K3_NIT (DTRF / K3_BK)    // 80
#define K3_A_OFF(buf) ((buf) * K3_BM * K3_LDH)
#define K3_B_OFF(buf) (2 * K3_BM * K3_LDH + (buf) * K3_BN * K3_LDH)
#define K3_SMEM ((2 * K3_BM * K3_LDH + 2 * K3_BN * K3_LDH) * 2)   // 64512 B

__global__ __launch_bounds__(256) void k3_f16(
    const float* __restrict__ lin_b,
    const float* __restrict__ og_p, const float* __restrict__ ob_p,
    float* __restrict__ out)
{
    extern __shared__ __align__(16) __half smh[];
    const uint32_t sbase = (uint32_t)__cvta_generic_to_shared(smh);

    const int t    = threadIdx.x;
    const int lane = t & 31;
    const int warp = t >> 5;
    const int wm   = warp >> 1;
    const int wn   = warp & 1;
    const int g    = lane >> 2;
    const int tg   = lane & 3;

    const int mbase = blockIdx.y * K3_BM;
    const int nbase = blockIdx.x * K3_BN;

    const int arow0 = t >> 3;
    const int ach   = t & 7;

    float acc[2][6][4] = {};

    auto issue = [&](int it, int buf) {
        const int kh = it * K3_BK;
#pragma unroll
        for (int i = 0; i < 4; i++) {
            int row = arow0 + i * 32;
            uint32_t dst = sbase +
                (uint32_t)(K3_A_OFF(buf) + row * K3_LDH + ach * 8) * 2;
            cp16(dst, g_yh + (size_t)(mbase + row) * DTRF + kh + ach * 8);
        }
#pragma unroll
        for (int i = 0; i < 3; i++) {
            int row = arow0 + i * 32;
            int br = nbase + row;
            if (br >= DOUT) br = 0;
            uint32_t dst = sbase +
                (uint32_t)(K3_B_OFF(buf) + row * K3_LDH + ach * 8) * 2;
            cp16(dst, g_wh + (size_t)br * DTRF + kh + ach * 8);
        }
        asm volatile("cp.async.commit_group;" ::: "memory");
    };

    issue(0, 0);

    for (int it = 0; it < K3_NIT; it++) {
        const int buf = it & 1;
        asm volatile("cp.async.wait_group 0;" ::: "memory");
        __syncthreads();
        if (it + 1 < K3_NIT) issue(it + 1, buf ^ 1);

#pragma unroll
        for (int ks = 0; ks < 4; ks++) {
            const int k0 = ks * 16;
            uint32_t af[2][4];
#pragma unroll
            for (int mi = 0; mi < 2; mi++) {
                const int rb = wm * 32 + mi * 16;
                uint32_t addr = sbase + (uint32_t)(K3_A_OFF(buf) +
                    (rb + (lane & 15)) * K3_LDH + k0 + (lane >> 4) * 8) * 2;
                ldsm_x4(af[mi][0], af[mi][1], af[mi][2], af[mi][3], addr);
            }
            uint32_t bf[3][4];
#pragma unroll
            for (int nh = 0; nh < 3; nh++) {
                const int nb = wn * 48 + nh * 16;
                uint32_t addr = sbase + (uint32_t)(K3_B_OFF(buf) +
                    (nb + (lane & 7) + ((lane >> 4) & 1) * 8) * K3_LDH +
                    k0 + ((lane >> 3) & 1) * 8) * 2;
                ldsm_x4(bf[nh][0], bf[nh][1], bf[nh][2], bf[nh][3], addr);
            }
#pragma unroll
            for (int mi = 0; mi < 2; mi++)
#pragma unroll
                for (int ni = 0; ni < 6; ni++) {
                    const int nh = ni >> 1, sub = ni & 1;
                    mma_f16(acc[mi][ni], af[mi],
                            bf[nh][sub * 2], bf[nh][sub * 2 + 1]);
                }
        }
    }

    const float og = og_p[0], ob = ob_p[0];
#pragma unroll
    for (int mi = 0; mi < 2; mi++) {
        const int m0 = mbase + wm * 32 + mi * 16 + g;
#pragma unroll
        for (int ni = 0; ni < 6; ni++) {
            const int n0 = nbase + wn * 48 + ni * 8 + tg * 2;
            if (n0 + 1 < DOUT) {
                const float lb0 = lin_b[n0], lb1 = lin_b[n0 + 1];
                out[(size_t)m0 * DOUT + n0]           = (acc[mi][ni][0] + lb0) * og + ob;
                out[(size_t)m0 * DOUT + n0 + 1]       = (acc[mi][ni][1] + lb1) * og + ob;
                out[(size_t)(m0 + 8) * DOUT + n0]     = (acc[mi][ni][2] + lb0) * og + ob;
                out[(size_t)(m0 + 8) * DOUT + n0 + 1] = (acc[mi][ni][3] + lb1) * og + ob;
            } else if (n0 < DOUT) {
                const float lb0 = lin_b[n0];
                out[(size_t)m0 * DOUT + n0]       = (acc[mi][ni][0] + lb0) * og + ob;
                out[(size_t)(m0 + 8) * DOUT + n0] = (acc[mi][ni][2] + lb0) * og + ob;
            }
        }
    }
}

// ---------------------------------------------------------------------------
extern "C" void kernel_launch(void* const* d_in, const int* in_sizes, int n_in,
                              void* d_out, int out_size)
{
    const float* x         = (const float*)d_in[0];
    const float* stdv      = (const float*)d_in[1];
    const float* meanv     = (const float*)d_in[2];
    const float* mat       = (const float*)d_in[3];
    const float* ln_g      = (const float*)d_in[4];
    const float* ln_b      = (const float*)d_in[5];
    const float* wq        = (const float*)d_in[6];
    const float* bq        = (const float*)d_in[7];
    const float* wk        = (const float*)d_in[8];
    const float* bk        = (const float*)d_in[9];
    const float* wv        = (const float*)d_in[10];
    const float* bv        = (const float*)d_in[11];
    const float* bt_w      = (const float*)d_in[12];
    const float* bt_b      = (const float*)d_in[13];
    const float* bt_gain   = (const float*)d_in[14];
    const float* bt_bias   = (const float*)d_in[15];
    const float* sup_gamma = (const float*)d_in[16];
    const float* sup_beta  = (const float*)d_in[17];
    const float* lin_w     = (const float*)d_in[18];
    const float* lin_b     = (const float*)d_in[19];
    const float* out_gain  = (const float*)d_in[20];
    const float* out_bias  = (const float*)d_in[21];
    float* out = (float*)d_out;

    const int smem2b = (64 * QK_ALD + 2 * 160 * QK_BLD) * 2;           // 36864
    const int smem2c = (64 * 164 + 160 * 36 + 32 * 33) * 4;            // 69248
    const int smem2d = (64 * 164 + 2 * 16 * 168) * 4;                  // 63488

    cudaFuncSetAttribute(k2b_qkv, cudaFuncAttributeMaxDynamicSharedMemorySize, smem2b);
    cudaFuncSetAttribute(k2c_attn, cudaFuncAttributeMaxDynamicSharedMemorySize, smem2c);
    cudaFuncSetAttribute(k2d_bt,  cudaFuncAttributeMaxDynamicSharedMemorySize, smem2d);
    cudaFuncSetAttribute(k3_f16,  cudaFuncAttributeMaxDynamicSharedMemorySize, K3_SMEM);

    k0_wh    <<<DOUT * DTRF / (8 * 256), 256>>>(lin_w);
    k0b_wsmall<<<3 * EE * EE / 256, 256>>>(wq, wk, wv);
    k0c_zero <<<(B_SZ * 2 * PADN + 255) / 256, 256>>>();
    k1_clgemm<<<dim3(40, 16), 256>>>(x, stdv, meanv, mat);
    k2a_ln   <<<B_SZ, 256>>>(ln_g, ln_b);
    k2b_qkv  <<<dim3(M2 / 64, 3), 256, smem2b>>>(bq, bk, bv);
    k2c_attn <<<B_SZ, 256, smem2c>>>();
    k2d_bt   <<<M2 / 64, 256, smem2d>>>(bt_w, bt_b, bt_gain, bt_bias,
                                        sup_gamma, sup_beta);
    k3_f16   <<<dim3((DOUT + K3_BN - 1) / K3_BN, B_SZ / K3_BM), 256, K3_SMEM>>>(
        lin_b, out_gain, out_bias, out);
}